// round 2
// baseline (speedup 1.0000x reference)
#include <cuda_runtime.h>

#define N_SP 4096
#define CDIM 64
#define MIDD 8
#define BDIM 4
#define TN 64
#define TM 64
#define KSTR 68
#define VSTR 68
#define PSTR 68
#define QDSTR 128

typedef unsigned long long ull;

// scratch (allocation-free rule: __device__ globals)
__device__ float g_q[BDIM * MIDD * N_SP];
__device__ float g_k[BDIM * MIDD * N_SP];
__device__ float g_v[BDIM * N_SP * CDIM];

__device__ __forceinline__ ull f2fma(ull a, ull b, ull c) {
    ull d;
    asm("fma.rn.f32x2 %0, %1, %2, %3;" : "=l"(d) : "l"(a), "l"(b), "l"(c));
    return d;
}
__device__ __forceinline__ ull pk2(float x, float y) {
    ull r;
    asm("mov.b64 %0, {%1, %2};" : "=l"(r) : "f"(x), "f"(y));
    return r;
}
__device__ __forceinline__ float2 upk2(ull v) {
    float2 r;
    asm("mov.b64 {%0, %1}, %2;" : "=f"(r.x), "=f"(r.y) : "l"(v));
    return r;
}

// ---------------------------------------------------------------------------
// Kernel 1: fused 1x1-conv projections q,k,v (unchanged layouts:
// q,k channel-major [b][c][n]; v position-major [b][n][c]).
// ---------------------------------------------------------------------------
__global__ __launch_bounds__(256) void qkv_kernel(
    const float* __restrict__ x,
    const float* __restrict__ Wq, const float* __restrict__ bq,
    const float* __restrict__ Wk, const float* __restrict__ bk,
    const float* __restrict__ Wv, const float* __restrict__ bv)
{
    __shared__ float sWq[MIDD * CDIM], sWk[MIDD * CDIM];
    __shared__ float sWv[CDIM * CDIM];
    __shared__ float sbq[MIDD], sbk[MIDD], sbv[CDIM];

    int tid = threadIdx.x;
    for (int i = tid; i < MIDD * CDIM; i += 256) { sWq[i] = Wq[i]; sWk[i] = Wk[i]; }
    for (int i = tid; i < CDIM * CDIM; i += 256) sWv[i] = Wv[i];
    if (tid < MIDD) { sbq[tid] = bq[tid]; sbk[tid] = bk[tid]; }
    if (tid < CDIM) sbv[tid] = bv[tid];
    __syncthreads();

    int g = blockIdx.x * 256 + tid;
    int b = g >> 12;
    int n = g & (N_SP - 1);

    float xr[CDIM];
    const float* xp = x + (size_t)(b * CDIM) * N_SP + n;
#pragma unroll
    for (int c = 0; c < CDIM; c++) xr[c] = xp[c * N_SP];

#pragma unroll
    for (int o = 0; o < MIDD; o++) {
        float aq = sbq[o], ak = sbk[o];
#pragma unroll
        for (int c = 0; c < CDIM; c++) {
            aq = fmaf(sWq[o * CDIM + c], xr[c], aq);
            ak = fmaf(sWk[o * CDIM + c], xr[c], ak);
        }
        g_q[(b * MIDD + o) * N_SP + n] = aq;
        g_k[(b * MIDD + o) * N_SP + n] = ak;
    }

    float* vp = g_v + (size_t)(b * N_SP + n) * CDIM;
#pragma unroll
    for (int o = 0; o < CDIM; o += 4) {
        float a0 = sbv[o], a1 = sbv[o + 1], a2 = sbv[o + 2], a3 = sbv[o + 3];
#pragma unroll
        for (int c = 0; c < CDIM; c++) {
            float xv = xr[c];
            a0 = fmaf(sWv[(o + 0) * CDIM + c], xv, a0);
            a1 = fmaf(sWv[(o + 1) * CDIM + c], xv, a1);
            a2 = fmaf(sWv[(o + 2) * CDIM + c], xv, a2);
            a3 = fmaf(sWv[(o + 3) * CDIM + c], xv, a3);
        }
        *reinterpret_cast<float4*>(vp + o) = make_float4(a0, a1, a2, a3);
    }
}

// ---------------------------------------------------------------------------
// Kernel 2: fused attention, f32x2 packed-FMA version.
// 128 threads, 64-row n-tile, loop over 64 m-tiles of 64.
// Scores: pack over n (Q duplicated in smem Qd[c][2n], K natural m-pairs).
//   wait -- packing detail: s2[i][jp] accumulates m-pairs; operands:
//   a = (k[m],k[m+1]) natural from Ks, b = (q_i,q_i) from duplicated Qd.
// PV: pack over c (V natural c-pairs from Vs[m][c]); p duplicated via 4 MOVs/m.
// ---------------------------------------------------------------------------
__global__ __launch_bounds__(128) void attn_kernel(
    const float* __restrict__ x,
    const float* __restrict__ gamma,
    float* __restrict__ out)
{
    __shared__ __align__(16) float Qd[MIDD * QDSTR];   // [c][2n] duplicated
    __shared__ __align__(16) float Ks[MIDD * KSTR];    // [c][m]
    __shared__ __align__(16) float Vs[TM * VSTR];      // [m][c]
    __shared__ __align__(16) float Ps[TM * PSTR];      // [m][n] (reused as Os[c][n])
    __shared__ float Ds[TN];

    int tid = threadIdx.x;
    int b = blockIdx.x >> 6;
    int ntile = blockIdx.x & 63;
    int n0g = ntile * TN;

    // score-phase mapping
    int tn = tid & 15;        // n group of 4
    int tm = tid >> 4;        // 0..7, m group of 8
    // PV-phase mapping
    int cg = tid & 7;         // c group of 8
    int ng = tid >> 3;        // 0..15, n group of 4

    // build duplicated Q tile: Qd[c][2j],[2j+1] = q[c][n0+j]
    if (tid < TN) {
#pragma unroll
        for (int c = 0; c < MIDD; c++) {
            float q = g_q[(b * MIDD + c) * N_SP + n0g + tid];
            Qd[c * QDSTR + 2 * tid] = q;
            Qd[c * QDSTR + 2 * tid + 1] = q;
        }
    }

    ull acc2[4][4];           // [n_i][c_pair], each = (c_even, c_odd) sums
#pragma unroll
    for (int i = 0; i < 4; i++)
#pragma unroll
        for (int j = 0; j < 4; j++) acc2[i][j] = 0ULL;
    float dacc[4] = {0.f, 0.f, 0.f, 0.f};

    const int kbase = (b * MIDD) * N_SP;

    for (int it = 0; it < N_SP / TM; it++) {
        int m0g = it * TM;
        __syncthreads();   // prev PV done (and Qd built on first iter)

        // --- load K tile [8][64]: 1 float4 per thread ---
        {
            int c = tid >> 4, col = (tid & 15) * 4;
            *reinterpret_cast<float4*>(&Ks[c * KSTR + col]) =
                *reinterpret_cast<const float4*>(&g_k[kbase + c * N_SP + m0g + col]);
        }
        // --- load V tile [64][64]: 8 float4 per thread ---
#pragma unroll
        for (int r = 0; r < 8; r++) {
            int f = tid + 128 * r;
            int row = f >> 4, off = (f & 15) * 4;
            *reinterpret_cast<float4*>(&Vs[row * VSTR + off]) =
                *reinterpret_cast<const float4*>(
                    &g_v[(size_t)(b * N_SP + m0g + row) * CDIM + off]);
        }
        __syncthreads();

        // ---- scores: s[i][j] = sum_c q[n0+tn*4+i][c] * k[m0+tm*8+j][c] ----
        // packed over m-pairs jp: s2[i][jp] = (s[i][2jp], s[i][2jp+1])
        ull s2[4][4];
#pragma unroll
        for (int i = 0; i < 4; i++)
#pragma unroll
            for (int j = 0; j < 4; j++) s2[i][j] = 0ULL;

#pragma unroll
        for (int c = 0; c < MIDD; c++) {
            ulonglong2 k01 = *reinterpret_cast<ulonglong2*>(&Ks[c * KSTR + tm * 8]);
            ulonglong2 k23 = *reinterpret_cast<ulonglong2*>(&Ks[c * KSTR + tm * 8 + 4]);
            ulonglong2 qa = *reinterpret_cast<ulonglong2*>(&Qd[c * QDSTR + tn * 8]);
            ulonglong2 qb = *reinterpret_cast<ulonglong2*>(&Qd[c * QDSTR + tn * 8 + 4]);
            // qa.x=(q0,q0) qa.y=(q1,q1) qb.x=(q2,q2) qb.y=(q3,q3)
            s2[0][0] = f2fma(qa.x, k01.x, s2[0][0]);
            s2[0][1] = f2fma(qa.x, k01.y, s2[0][1]);
            s2[0][2] = f2fma(qa.x, k23.x, s2[0][2]);
            s2[0][3] = f2fma(qa.x, k23.y, s2[0][3]);
            s2[1][0] = f2fma(qa.y, k01.x, s2[1][0]);
            s2[1][1] = f2fma(qa.y, k01.y, s2[1][1]);
            s2[1][2] = f2fma(qa.y, k23.x, s2[1][2]);
            s2[1][3] = f2fma(qa.y, k23.y, s2[1][3]);
            s2[2][0] = f2fma(qb.x, k01.x, s2[2][0]);
            s2[2][1] = f2fma(qb.x, k01.y, s2[2][1]);
            s2[2][2] = f2fma(qb.x, k23.x, s2[2][2]);
            s2[2][3] = f2fma(qb.x, k23.y, s2[2][3]);
            s2[3][0] = f2fma(qb.y, k01.x, s2[3][0]);
            s2[3][1] = f2fma(qb.y, k01.y, s2[3][1]);
            s2[3][2] = f2fma(qb.y, k23.x, s2[3][2]);
            s2[3][3] = f2fma(qb.y, k23.y, s2[3][3]);
        }

        // ---- exp + transposed store to Ps[m][n] + denom partials ----
#pragma unroll
        for (int jp = 0; jp < 4; jp++) {
            float2 e0 = upk2(s2[0][jp]);
            float2 e1 = upk2(s2[1][jp]);
            float2 e2 = upk2(s2[2][jp]);
            float2 e3 = upk2(s2[3][jp]);
            float p00 = __expf(e0.x), p01 = __expf(e0.y);
            float p10 = __expf(e1.x), p11 = __expf(e1.y);
            float p20 = __expf(e2.x), p21 = __expf(e2.y);
            float p30 = __expf(e3.x), p31 = __expf(e3.y);
            dacc[0] += p00 + p01; dacc[1] += p10 + p11;
            dacc[2] += p20 + p21; dacc[3] += p30 + p31;
            int m0 = tm * 8 + 2 * jp;
            *reinterpret_cast<float4*>(&Ps[m0 * PSTR + tn * 4]) =
                make_float4(p00, p10, p20, p30);
            *reinterpret_cast<float4*>(&Ps[(m0 + 1) * PSTR + tn * 4]) =
                make_float4(p01, p11, p21, p31);
        }
        __syncthreads();

        // ---- PV: O[n][c] += P[m][n] * V[m][c], packed over c-pairs ----
#pragma unroll 4
        for (int m = 0; m < TM; m++) {
            float4 pf = *reinterpret_cast<float4*>(&Ps[m * PSTR + ng * 4]);
            ull pd0 = pk2(pf.x, pf.x);
            ull pd1 = pk2(pf.y, pf.y);
            ull pd2 = pk2(pf.z, pf.z);
            ull pd3 = pk2(pf.w, pf.w);
            ulonglong2 va = *reinterpret_cast<ulonglong2*>(&Vs[m * VSTR + cg * 8]);
            ulonglong2 vb = *reinterpret_cast<ulonglong2*>(&Vs[m * VSTR + cg * 8 + 4]);
            acc2[0][0] = f2fma(va.x, pd0, acc2[0][0]);
            acc2[0][1] = f2fma(va.y, pd0, acc2[0][1]);
            acc2[0][2] = f2fma(vb.x, pd0, acc2[0][2]);
            acc2[0][3] = f2fma(vb.y, pd0, acc2[0][3]);
            acc2[1][0] = f2fma(va.x, pd1, acc2[1][0]);
            acc2[1][1] = f2fma(va.y, pd1, acc2[1][1]);
            acc2[1][2] = f2fma(vb.x, pd1, acc2[1][2]);
            acc2[1][3] = f2fma(vb.y, pd1, acc2[1][3]);
            acc2[2][0] = f2fma(va.x, pd2, acc2[2][0]);
            acc2[2][1] = f2fma(va.y, pd2, acc2[2][1]);
            acc2[2][2] = f2fma(vb.x, pd2, acc2[2][2]);
            acc2[2][3] = f2fma(vb.y, pd2, acc2[2][3]);
            acc2[3][0] = f2fma(va.x, pd3, acc2[3][0]);
            acc2[3][1] = f2fma(va.y, pd3, acc2[3][1]);
            acc2[3][2] = f2fma(vb.x, pd3, acc2[3][2]);
            acc2[3][3] = f2fma(vb.y, pd3, acc2[3][3]);
        }
    }

    // ---- denominator reduction (stage into Ks region, 8x64) ----
    __syncthreads();
    *reinterpret_cast<float4*>(&Ks[tm * 64 + tn * 4]) =
        make_float4(dacc[0], dacc[1], dacc[2], dacc[3]);
    __syncthreads();
    if (tid < TN) {
        float s = 0.f;
#pragma unroll
        for (int r = 0; r < 8; r++) s += Ks[r * 64 + tid];
        Ds[tid] = s;
    }
    __syncthreads();

    // ---- scale + stage Os[c][n] into Ps region ----
    float gm = gamma[0];
    float rinv[4];
#pragma unroll
    for (int i = 0; i < 4; i++) rinv[i] = gm / Ds[ng * 4 + i];

#pragma unroll
    for (int i = 0; i < 4; i++) {
#pragma unroll
        for (int cp = 0; cp < 4; cp++) {
            float2 v = upk2(acc2[i][cp]);
            int c0 = cg * 8 + 2 * cp;
            Ps[c0 * PSTR + ng * 4 + i] = v.x * rinv[i];
            Ps[(c0 + 1) * PSTR + ng * 4 + i] = v.y * rinv[i];
        }
    }
    __syncthreads();

    // ---- coalesced epilogue: out[b][c][n] = Os + x ----
#pragma unroll
    for (int r = 0; r < 8; r++) {
        int f = tid + 128 * r;
        int c = f >> 4, off = (f & 15) * 4;
        float4 o = *reinterpret_cast<float4*>(&Ps[c * PSTR + off]);
        size_t base = (size_t)(b * CDIM + c) * N_SP + n0g + off;
        float4 xv = *reinterpret_cast<const float4*>(&x[base]);
        o.x += xv.x; o.y += xv.y; o.z += xv.z; o.w += xv.w;
        *reinterpret_cast<float4*>(&out[base]) = o;
    }
}

// ---------------------------------------------------------------------------
extern "C" void kernel_launch(void* const* d_in, const int* in_sizes, int n_in,
                              void* d_out, int out_size)
{
    const float* x     = (const float*)d_in[0];
    const float* Wq    = (const float*)d_in[1];
    const float* bq    = (const float*)d_in[2];
    const float* Wk    = (const float*)d_in[3];
    const float* bk    = (const float*)d_in[4];
    const float* Wv    = (const float*)d_in[5];
    const float* bv    = (const float*)d_in[6];
    const float* gamma = (const float*)d_in[7];
    float* out = (float*)d_out;

    qkv_kernel<<<(BDIM * N_SP) / 256, 256>>>(x, Wq, bq, Wk, bk, Wv, bv);
    attn_kernel<<<BDIM * (N_SP / TN), 128>>>(x, gamma, out);
}

// round 4
// speedup vs baseline: 6.5678x; 6.5678x over previous
#include <cuda_runtime.h>
#include <cuda_bf16.h>
#include <stdint.h>

#define N_SP 4096
#define CDIM 64
#define MIDD 8
#define BDIM 4
#define NB 128            // n rows per CTA
#define MB 64             // m per iteration
#define NITER (N_SP / MB)

// smem layout (union: loop phase vs epilogue phase)
#define QS_OFF 0                  // [128 rows][16B]
#define KS_OFF 2048               // [64 rows][16B]
#define VS_OFF 3072               // [64 c][72 bf16] (144B stride)
#define VSTRB 144
#define OSTR 132                  // floats
#define SMEM_BYTES (CDIM * OSTR * 4)       // 33792 (>= loop usage 12288)

// bf16 scratch (allocation-free rule: __device__ globals)
__device__ __nv_bfloat16 g_qb[BDIM * N_SP * MIDD];   // [b][n][8c]
__device__ __nv_bfloat16 g_kb[BDIM * N_SP * MIDD];   // [b][m][8c]
__device__ __nv_bfloat16 g_vb[BDIM * CDIM * N_SP];   // [b][c][m]

__device__ __forceinline__ uint32_t smem_u32(const void* p) {
    uint32_t a;
    asm("{ .reg .u64 t; cvta.to.shared.u64 t, %1; cvt.u32.u64 %0, t; }"
        : "=r"(a) : "l"(p));
    return a;
}
__device__ __forceinline__ void ldsm_x2(uint32_t& r0, uint32_t& r1, uint32_t a) {
    asm volatile("ldmatrix.sync.aligned.m8n8.x2.shared.b16 {%0,%1}, [%2];"
                 : "=r"(r0), "=r"(r1) : "r"(a));
}
__device__ __forceinline__ void ldsm_x4(uint32_t& r0, uint32_t& r1,
                                        uint32_t& r2, uint32_t& r3, uint32_t a) {
    asm volatile("ldmatrix.sync.aligned.m8n8.x4.shared.b16 {%0,%1,%2,%3}, [%4];"
                 : "=r"(r0), "=r"(r1), "=r"(r2), "=r"(r3) : "r"(a));
}
// D(16x8,f32) = A(16x8 bf16) * B(8x8 bf16), C=0
__device__ __forceinline__ void mma_16808(float* d, uint32_t a0, uint32_t a1,
                                          uint32_t b0) {
    asm volatile(
        "mma.sync.aligned.m16n8k8.row.col.f32.bf16.bf16.f32 "
        "{%0,%1,%2,%3}, {%4,%5}, {%6}, {%7,%7,%7,%7};"
        : "=f"(d[0]), "=f"(d[1]), "=f"(d[2]), "=f"(d[3])
        : "r"(a0), "r"(a1), "r"(b0), "f"(0.f));
}
// D(16x8,f32) += A(16x16 bf16) * B(16x8 bf16)
__device__ __forceinline__ void mma_16816(float* d, const uint32_t* a,
                                          uint32_t b0, uint32_t b1) {
    asm volatile(
        "mma.sync.aligned.m16n8k16.row.col.f32.bf16.bf16.f32 "
        "{%0,%1,%2,%3}, {%4,%5,%6,%7}, {%8,%9}, {%0,%1,%2,%3};"
        : "+f"(d[0]), "+f"(d[1]), "+f"(d[2]), "+f"(d[3])
        : "r"(a[0]), "r"(a[1]), "r"(a[2]), "r"(a[3]), "r"(b0), "r"(b1));
}
__device__ __forceinline__ uint32_t pack_bf(float even, float odd) {
    uint32_t r;   // lo half = even element (first k), hi = odd
    asm("cvt.rn.bf16x2.f32 %0, %1, %2;" : "=r"(r) : "f"(odd), "f"(even));
    return r;
}

// ---------------------------------------------------------------------------
// Kernel 1: 1x1-conv projections -> bf16 q,k [b][n][8c]; v [b][c][m].
// ---------------------------------------------------------------------------
__global__ __launch_bounds__(256) void qkv_kernel(
    const float* __restrict__ x,
    const float* __restrict__ Wq, const float* __restrict__ bq,
    const float* __restrict__ Wk, const float* __restrict__ bk,
    const float* __restrict__ Wv, const float* __restrict__ bv)
{
    __shared__ float sWq[MIDD * CDIM], sWk[MIDD * CDIM];
    __shared__ float sWv[CDIM * CDIM];
    __shared__ float sbq[MIDD], sbk[MIDD], sbv[CDIM];

    int tid = threadIdx.x;
    for (int i = tid; i < MIDD * CDIM; i += 256) { sWq[i] = Wq[i]; sWk[i] = Wk[i]; }
    for (int i = tid; i < CDIM * CDIM; i += 256) sWv[i] = Wv[i];
    if (tid < MIDD) { sbq[tid] = bq[tid]; sbk[tid] = bk[tid]; }
    if (tid < CDIM) sbv[tid] = bv[tid];
    __syncthreads();

    int g = blockIdx.x * 256 + tid;
    int b = g >> 12;
    int n = g & (N_SP - 1);

    float xr[CDIM];
    const float* xp = x + (size_t)(b * CDIM) * N_SP + n;
#pragma unroll
    for (int c = 0; c < CDIM; c++) xr[c] = xp[c * N_SP];

    float aq[MIDD], ak[MIDD];
#pragma unroll
    for (int o = 0; o < MIDD; o++) {
        float q = sbq[o], k = sbk[o];
#pragma unroll
        for (int c = 0; c < CDIM; c++) {
            q = fmaf(sWq[o * CDIM + c], xr[c], q);
            k = fmaf(sWk[o * CDIM + c], xr[c], k);
        }
        aq[o] = q; ak[o] = k;
    }
    {
        uint4 u;
        __nv_bfloat162 t0 = __floats2bfloat162_rn(aq[0], aq[1]);
        __nv_bfloat162 t1 = __floats2bfloat162_rn(aq[2], aq[3]);
        __nv_bfloat162 t2 = __floats2bfloat162_rn(aq[4], aq[5]);
        __nv_bfloat162 t3 = __floats2bfloat162_rn(aq[6], aq[7]);
        u.x = *(uint32_t*)&t0; u.y = *(uint32_t*)&t1;
        u.z = *(uint32_t*)&t2; u.w = *(uint32_t*)&t3;
        *(uint4*)(g_qb + (size_t)(b * N_SP + n) * MIDD) = u;
        t0 = __floats2bfloat162_rn(ak[0], ak[1]);
        t1 = __floats2bfloat162_rn(ak[2], ak[3]);
        t2 = __floats2bfloat162_rn(ak[4], ak[5]);
        t3 = __floats2bfloat162_rn(ak[6], ak[7]);
        u.x = *(uint32_t*)&t0; u.y = *(uint32_t*)&t1;
        u.z = *(uint32_t*)&t2; u.w = *(uint32_t*)&t3;
        *(uint4*)(g_kb + (size_t)(b * N_SP + n) * MIDD) = u;
    }
#pragma unroll
    for (int o = 0; o < CDIM; o++) {
        float a = sbv[o];
#pragma unroll
        for (int c = 0; c < CDIM; c++) a = fmaf(sWv[o * CDIM + c], xr[c], a);
        g_vb[(size_t)(b * CDIM + o) * N_SP + n] = __float2bfloat16(a);
    }
}

// ---------------------------------------------------------------------------
// Kernel 2: flash attention on HMMA (mma.sync), P stays in registers.
// 8 warps; warp w owns n-rows [w*16, w*16+16). m loop of 64.
// ---------------------------------------------------------------------------
__global__ __launch_bounds__(256, 2) void attn_kernel(
    const float* __restrict__ x,
    const float* __restrict__ gamma,
    float* __restrict__ out)
{
    __shared__ __align__(16) char smem[SMEM_BYTES];
    uint32_t sb = smem_u32(smem);

    int tid = threadIdx.x;
    int w = tid >> 5;
    int t = tid & 31;
    int b = blockIdx.x >> 5;
    int n0g = (blockIdx.x & 31) * NB;

    // ---- stage Q tile [128][16B], then per-warp A-frag (x2 ldmatrix) ----
    if (tid < NB) {
        *(uint4*)(smem + QS_OFF + tid * 16) =
            *(const uint4*)(g_qb + (size_t)(b * N_SP + n0g + tid) * MIDD);
    }
    __syncthreads();
    uint32_t qa0, qa1;
    ldsm_x2(qa0, qa1, sb + QS_OFF + (w * 16 + (t & 15)) * 16);

    // ---- prefetch tile 0 into registers ----
    uint4 ku, vu0, vu1;
    {
        if (tid < MB)
            ku = *(const uint4*)(g_kb + (size_t)(b * N_SP + tid) * MIDD);
        int c0 = tid >> 3, mc0 = tid & 7;
        vu0 = *(const uint4*)(g_vb + (size_t)(b * CDIM + c0) * N_SP + mc0 * 8);
        int f1 = tid + 256;
        int c1 = f1 >> 3, mc1 = f1 & 7;
        vu1 = *(const uint4*)(g_vb + (size_t)(b * CDIM + c1) * N_SP + mc1 * 8);
    }

    float oacc[8][4];
#pragma unroll
    for (int g2 = 0; g2 < 8; g2++)
#pragma unroll
        for (int j = 0; j < 4; j++) oacc[g2][j] = 0.f;
    float dlo = 0.f, dhi = 0.f;

    for (int it = 0; it < NITER; it++) {
        __syncthreads();   // previous compute done reading smem
        // store prefetched tile
        if (tid < MB) *(uint4*)(smem + KS_OFF + tid * 16) = ku;
        {
            int c0 = tid >> 3, mc0 = tid & 7;
            *(uint4*)(smem + VS_OFF + c0 * VSTRB + mc0 * 16) = vu0;
            int f1 = tid + 256;
            int c1 = f1 >> 3, mc1 = f1 & 7;
            *(uint4*)(smem + VS_OFF + c1 * VSTRB + mc1 * 16) = vu1;
        }
        __syncthreads();

        // prefetch next tile (latency hidden behind compute below)
        if (it + 1 < NITER) {
            int m0n = (it + 1) * MB;
            if (tid < MB)
                ku = *(const uint4*)(g_kb + (size_t)(b * N_SP + m0n + tid) * MIDD);
            int c0 = tid >> 3, mc0 = tid & 7;
            vu0 = *(const uint4*)(g_vb + (size_t)(b * CDIM + c0) * N_SP + m0n + mc0 * 8);
            int f1 = tid + 256;
            int c1 = f1 >> 3, mc1 = f1 & 7;
            vu1 = *(const uint4*)(g_vb + (size_t)(b * CDIM + c1) * N_SP + m0n + mc1 * 8);
        }

        // ---- K B-frags: 8 m-groups via 2x ldmatrix.x4 ----
        uint32_t kb[8];
        ldsm_x4(kb[0], kb[1], kb[2], kb[3], sb + KS_OFF + t * 16);
        ldsm_x4(kb[4], kb[5], kb[6], kb[7], sb + KS_OFF + (32 + t) * 16);

        // ---- QK + exp + pack P (A-frags for 4 K-steps) ----
        uint32_t p[16];
#pragma unroll
        for (int g2 = 0; g2 < 8; g2++) {
            float d[4];
            mma_16808(d, qa0, qa1, kb[g2]);
            float e0 = __expf(d[0]), e1 = __expf(d[1]);
            float e2 = __expf(d[2]), e3 = __expf(d[3]);
            dlo += e0 + e1; dhi += e2 + e3;
            int ks = g2 >> 1, half = g2 & 1;
            p[ks * 4 + half * 2]     = pack_bf(e0, e1);
            p[ks * 4 + half * 2 + 1] = pack_bf(e2, e3);
        }

        // ---- PV: 4 K-steps x 8 c-groups (V frags via ldmatrix.x4) ----
#pragma unroll
        for (int ks = 0; ks < 4; ks++) {
#pragma unroll
            for (int gp = 0; gp < 4; gp++) {
                int crow = gp * 16 + ((t & 16) >> 1) + (t & 7);
                int col = ks * 16 + ((t >> 3) & 1) * 8;
                uint32_t r0, r1, r2, r3;
                ldsm_x4(r0, r1, r2, r3, sb + VS_OFF + crow * VSTRB + col * 2);
                mma_16816(oacc[gp * 2 + 0], &p[ks * 4], r0, r1);
                mma_16816(oacc[gp * 2 + 1], &p[ks * 4], r2, r3);
            }
        }
    }

    // ---- denominator: reduce over the 4 lanes of each row quad ----
    dlo += __shfl_xor_sync(0xFFFFFFFFu, dlo, 1);
    dlo += __shfl_xor_sync(0xFFFFFFFFu, dlo, 2);
    dhi += __shfl_xor_sync(0xFFFFFFFFu, dhi, 1);
    dhi += __shfl_xor_sync(0xFFFFFFFFu, dhi, 2);
    float gm = gamma[0];
    float rlo = gm / dlo, rhi = gm / dhi;

    // ---- stage O to smem [c][n] and write out coalesced ----
    __syncthreads();   // loop smem dead; reuse as Os
    float* Os = (float*)smem;
    int nlo = w * 16 + (t >> 2);
    int col0 = 2 * (t & 3);
#pragma unroll
    for (int g2 = 0; g2 < 8; g2++) {
        int c0 = g2 * 8 + col0;
        Os[c0 * OSTR + nlo]           = oacc[g2][0] * rlo;
        Os[(c0 + 1) * OSTR + nlo]     = oacc[g2][1] * rlo;
        Os[c0 * OSTR + nlo + 8]       = oacc[g2][2] * rhi;
        Os[(c0 + 1) * OSTR + nlo + 8] = oacc[g2][3] * rhi;
    }
    __syncthreads();

#pragma unroll
    for (int rr = 0; rr < 8; rr++) {
        int f = tid + 256 * rr;          // float4 id: 64 c-rows x 32 per row
        int c = f >> 5, j = f & 31;
        float4 o = *(float4*)&Os[c * OSTR + j * 4];
        size_t base = (size_t)(b * CDIM + c) * N_SP + n0g + j * 4;
        float4 xv = *(const float4*)&x[base];
        o.x += xv.x; o.y += xv.y; o.z += xv.z; o.w += xv.w;
        *(float4*)&out[base] = o;
    }
}

// ---------------------------------------------------------------------------
extern "C" void kernel_launch(void* const* d_in, const int* in_sizes, int n_in,
                              void* d_out, int out_size)
{
    const float* x     = (const float*)d_in[0];
    const float* Wq    = (const float*)d_in[1];
    const float* bq    = (const float*)d_in[2];
    const float* Wk    = (const float*)d_in[3];
    const float* bk    = (const float*)d_in[4];
    const float* Wv    = (const float*)d_in[5];
    const float* bv    = (const float*)d_in[6];
    const float* gamma = (const float*)d_in[7];
    float* out = (float*)d_out;

    qkv_kernel<<<(BDIM * N_SP) / 256, 256>>>(x, Wq, bq, Wk, bk, Wv, bv);
    attn_kernel<<<BDIM * (N_SP / NB), 256>>>(x, gamma, out);
}

// round 6
// speedup vs baseline: 8.1122x; 1.2352x over previous
#include <cuda_runtime.h>
#include <cuda_bf16.h>
#include <stdint.h>

#define N_SP 4096
#define CDIM 64
#define MIDD 8
#define BDIM 4
#define NB 64             // n rows per CTA
#define MB 64             // m per tile
#define NSTEP 32          // each m-group does 32 tiles of 64 (= 4096/64/2 groups)
#define LOG2E 1.4426950408889634f

// ---- attn smem layout (bytes) ----
#define QS_OFF 0                      // 64 rows x 16B
#define KB_OFF 1024                   // 4 bufs x 64 x 16B
#define VB_OFF 5120                   // 4 bufs x 64c x 144B
#define VSTRB 144
#define SM_TOTAL (5120 + 4 * 64 * VSTRB)   // 41984
// epilogue overlays (loop buffers dead):
#define EP_DSM 0                      // 64 floats
#define EP_RS  512                    // 64 floats
#define EP_OS  4096                   // 64c x 68 floats
#define OSTR 68

// bf16 scratch (allocation-free rule: __device__ globals)
__device__ __nv_bfloat16 g_qb[BDIM * N_SP * MIDD];   // [b][n][8c], pre-scaled by log2e
__device__ __nv_bfloat16 g_kb[BDIM * N_SP * MIDD];   // [b][m][8c]
__device__ __nv_bfloat16 g_vb[BDIM * CDIM * N_SP];   // [b][c][m]

__device__ __forceinline__ uint32_t smem_u32(const void* p) {
    uint32_t a;
    asm("{ .reg .u64 t; cvta.to.shared.u64 t, %1; cvt.u32.u64 %0, t; }"
        : "=r"(a) : "l"(p));
    return a;
}
__device__ __forceinline__ void ldsm_x4(uint32_t& r0, uint32_t& r1,
                                        uint32_t& r2, uint32_t& r3, uint32_t a) {
    asm volatile("ldmatrix.sync.aligned.m8n8.x4.shared.b16 {%0,%1,%2,%3}, [%4];"
                 : "=r"(r0), "=r"(r1), "=r"(r2), "=r"(r3) : "r"(a));
}
__device__ __forceinline__ void mma_16808(float* d, uint32_t a0, uint32_t a1,
                                          uint32_t b0) {
    asm volatile(
        "mma.sync.aligned.m16n8k8.row.col.f32.bf16.bf16.f32 "
        "{%0,%1,%2,%3}, {%4,%5}, {%6}, {%7,%7,%7,%7};"
        : "=f"(d[0]), "=f"(d[1]), "=f"(d[2]), "=f"(d[3])
        : "r"(a0), "r"(a1), "r"(b0), "f"(0.f));
}
__device__ __forceinline__ void mma_16816(float* d, const uint32_t* a,
                                          uint32_t b0, uint32_t b1) {
    asm volatile(
        "mma.sync.aligned.m16n8k16.row.col.f32.bf16.bf16.f32 "
        "{%0,%1,%2,%3}, {%4,%5,%6,%7}, {%8,%9}, {%0,%1,%2,%3};"
        : "+f"(d[0]), "+f"(d[1]), "+f"(d[2]), "+f"(d[3])
        : "r"(a[0]), "r"(a[1]), "r"(a[2]), "r"(a[3]), "r"(b0), "r"(b1));
}
__device__ __forceinline__ uint32_t pack_bf(float even, float odd) {
    uint32_t r;
    asm("cvt.rn.bf16x2.f32 %0, %1, %2;" : "=r"(r) : "f"(odd), "f"(even));
    return r;
}
__device__ __forceinline__ float ex2(float v) {
    float r;
    asm("ex2.approx.f32 %0, %1;" : "=f"(r) : "f"(v));
    return r;
}
__device__ __forceinline__ void cpasync16(uint32_t dst, const void* src) {
    asm volatile("cp.async.ca.shared.global [%0], [%1], 16;" :: "r"(dst), "l"(src));
}
#define CP_COMMIT() asm volatile("cp.async.commit_group;" ::: "memory")

// ---------------------------------------------------------------------------
// Kernel 1: 1x1-conv projections. 2 threads per position:
//   h=0: q (8 outs, pre-scaled by log2e) + v channels 0..31
//   h=1: k (8 outs) + v channels 32..63
// grid = 256 blocks x 128 threads; block -> (p0 = (blk>>1)*128, h = blk&1).
// ---------------------------------------------------------------------------
__global__ __launch_bounds__(128) void qkv_kernel(
    const float* __restrict__ x,
    const float* __restrict__ Wq, const float* __restrict__ bq,
    const float* __restrict__ Wk, const float* __restrict__ bk,
    const float* __restrict__ Wv, const float* __restrict__ bv)
{
    __shared__ float sWa[MIDD * CDIM];     // Wq*log2e or Wk
    __shared__ float sWv[32 * CDIM];       // my half of Wv
    __shared__ float sba[MIDD], sbv[32];

    int tid = threadIdx.x;
    int h = blockIdx.x & 1;
    int p = (blockIdx.x >> 1) * 128 + tid;
    int b = p >> 12;
    int n = p & (N_SP - 1);

    const float* Wa = h ? Wk : Wq;
    const float* ba = h ? bk : bq;
    float wscale = h ? 1.f : LOG2E;
    for (int i = tid; i < MIDD * CDIM; i += 128) sWa[i] = Wa[i] * wscale;
    for (int i = tid; i < 32 * CDIM; i += 128) sWv[i] = Wv[h * 32 * CDIM + i];
    if (tid < MIDD) sba[tid] = ba[tid] * wscale;
    if (tid < 32) sbv[tid] = bv[h * 32 + tid];
    __syncthreads();

    float xr[CDIM];
    const float* xp = x + (size_t)(b * CDIM) * N_SP + n;
#pragma unroll
    for (int c = 0; c < CDIM; c++) xr[c] = xp[c * N_SP];

    // q or k (8 outputs)
    float aa[MIDD];
#pragma unroll
    for (int o = 0; o < MIDD; o++) {
        float a = sba[o];
#pragma unroll
        for (int c = 0; c < CDIM; c++) a = fmaf(sWa[o * CDIM + c], xr[c], a);
        aa[o] = a;
    }
    {
        uint4 u;
        __nv_bfloat162 t0 = __floats2bfloat162_rn(aa[0], aa[1]);
        __nv_bfloat162 t1 = __floats2bfloat162_rn(aa[2], aa[3]);
        __nv_bfloat162 t2 = __floats2bfloat162_rn(aa[4], aa[5]);
        __nv_bfloat162 t3 = __floats2bfloat162_rn(aa[6], aa[7]);
        u.x = *(uint32_t*)&t0; u.y = *(uint32_t*)&t1;
        u.z = *(uint32_t*)&t2; u.w = *(uint32_t*)&t3;
        __nv_bfloat16* dst = (h ? g_kb : g_qb) + (size_t)(b * N_SP + n) * MIDD;
        *(uint4*)dst = u;
    }

    // v half (32 outputs, chunks of 8 to bound live registers)
#pragma unroll
    for (int ob = 0; ob < 4; ob++) {
        float acc[8];
#pragma unroll
        for (int j = 0; j < 8; j++) acc[j] = sbv[ob * 8 + j];
#pragma unroll
        for (int c = 0; c < CDIM; c++) {
            float xv = xr[c];
#pragma unroll
            for (int j = 0; j < 8; j++)
                acc[j] = fmaf(sWv[(ob * 8 + j) * CDIM + c], xv, acc[j]);
        }
#pragma unroll
        for (int j = 0; j < 8; j++) {
            int o = h * 32 + ob * 8 + j;
            g_vb[(size_t)(b * CDIM + o) * N_SP + n] = __float2bfloat16(acc[j]);
        }
    }
}

// ---------------------------------------------------------------------------
// Kernel 2: HMMA flash attention. CTA = 128 thr (4 warps), NB=64 n-rows.
// warp w: m-group mg = w&1 (even/odd m-tiles), rows wrow = (w>>1)*32 .. +32.
// Each warp: 32 iters of MB=64; P stays in registers; cp.async double-buffer.
// ---------------------------------------------------------------------------
__global__ __launch_bounds__(128, 2) void attn_kernel(
    const float* __restrict__ x,
    const float* __restrict__ gamma,
    float* __restrict__ out)
{
    __shared__ __align__(16) char smem[SM_TOTAL];
    uint32_t sb = smem_u32(smem);

    int tid = threadIdx.x;
    int w = tid >> 5;
    int t = tid & 31;
    int mg = w & 1;
    int wrow = (w >> 1) * 32;
    int b = blockIdx.x >> 6;
    int n0 = (blockIdx.x & 63) * NB;

    // ---- stage Q tile [64 rows][16B] ----
    if (tid < NB) {
        *(uint4*)(smem + QS_OFF + tid * 16) =
            *(const uint4*)(g_qb + (size_t)(b * N_SP + n0 + tid) * MIDD);
    }

    // ---- prologue: issue tiles 0,1 into parity-0 buffers ----
    {
#pragma unroll
        for (int i = 0; i < 9; i++) {
            int ch = tid + 128 * i;
            int tile = (ch >= 576);
            int c2 = ch - tile * 576;
            if (c2 < 512) {
                int c = c2 >> 3, q8 = c2 & 7;
                cpasync16(sb + VB_OFF + (tile * 2) * (64 * VSTRB) + c * VSTRB + q8 * 16,
                          g_vb + (size_t)(b * CDIM + c) * N_SP + tile * MB + q8 * 8);
            } else {
                int row = c2 - 512;
                cpasync16(sb + KB_OFF + (tile * 2) * 1024 + row * 16,
                          g_kb + (size_t)(b * N_SP + tile * MB + row) * MIDD);
            }
        }
        CP_COMMIT();
    }
    __syncthreads();

    // Q A-frags: 2 row-frags (rows wrow..wrow+31)
    uint32_t qa[4];
    ldsm_x4(qa[0], qa[1], qa[2], qa[3], sb + QS_OFF + (wrow + t) * 16);

    float o0[8][4], o1[8][4];
#pragma unroll
    for (int g2 = 0; g2 < 8; g2++)
#pragma unroll
        for (int j = 0; j < 4; j++) { o0[g2][j] = 0.f; o1[g2][j] = 0.f; }
    float d0A = 0.f, d0B = 0.f, d1A = 0.f, d1B = 0.f;

    for (int step = 0; step < NSTEP; step++) {
        // issue next pair of tiles
        if (step + 1 < NSTEP) {
            int par = (step + 1) & 1;
            int tg0 = 2 * (step + 1);
#pragma unroll
            for (int i = 0; i < 9; i++) {
                int ch = tid + 128 * i;
                int tile = (ch >= 576);
                int c2 = ch - tile * 576;
                int tg = tg0 + tile;
                if (c2 < 512) {
                    int c = c2 >> 3, q8 = c2 & 7;
                    cpasync16(sb + VB_OFF + (tile * 2 + par) * (64 * VSTRB) + c * VSTRB + q8 * 16,
                              g_vb + (size_t)(b * CDIM + c) * N_SP + tg * MB + q8 * 8);
                } else {
                    int row = c2 - 512;
                    cpasync16(sb + KB_OFF + (tile * 2 + par) * 1024 + row * 16,
                              g_kb + (size_t)(b * N_SP + tg * MB + row) * MIDD);
                }
            }
            CP_COMMIT();
            asm volatile("cp.async.wait_group 1;" ::: "memory");
        } else {
            asm volatile("cp.async.wait_group 0;" ::: "memory");
        }
        __syncthreads();

        int par = step & 1;
        uint32_t kbase = sb + KB_OFF + (mg * 2 + par) * 1024;
        uint32_t vbase = sb + VB_OFF + (mg * 2 + par) * (64 * VSTRB);

        // K B-frags: 8 m-groups
        uint32_t kb[8];
        ldsm_x4(kb[0], kb[1], kb[2], kb[3], kbase + t * 16);
        ldsm_x4(kb[4], kb[5], kb[6], kb[7], kbase + (32 + t) * 16);

        // QK + exp2 + pack P for both row-frags
        uint32_t p0[16], p1[16];
#pragma unroll
        for (int g2 = 0; g2 < 8; g2++) {
            float d0[4], d1[4];
            mma_16808(d0, qa[0], qa[1], kb[g2]);
            mma_16808(d1, qa[2], qa[3], kb[g2]);
            float e00 = ex2(d0[0]), e01 = ex2(d0[1]), e02 = ex2(d0[2]), e03 = ex2(d0[3]);
            float e10 = ex2(d1[0]), e11 = ex2(d1[1]), e12 = ex2(d1[2]), e13 = ex2(d1[3]);
            d0A += e00 + e01; d0B += e02 + e03;
            d1A += e10 + e11; d1B += e12 + e13;
            int ks = g2 >> 1, hf = g2 & 1;
            p0[ks * 4 + hf * 2]     = pack_bf(e00, e01);
            p0[ks * 4 + hf * 2 + 1] = pack_bf(e02, e03);
            p1[ks * 4 + hf * 2]     = pack_bf(e10, e11);
            p1[ks * 4 + hf * 2 + 1] = pack_bf(e12, e13);
        }

        // PV: 4 K-steps x 4 ldsm groups; each V frag feeds both row-frags
#pragma unroll
        for (int ks = 0; ks < 4; ks++) {
#pragma unroll
            for (int gp = 0; gp < 4; gp++) {
                int crow = gp * 16 + ((t & 16) >> 1) + (t & 7);
                int col = ks * 16 + ((t >> 3) & 1) * 8;
                uint32_t r0, r1, r2, r3;
                ldsm_x4(r0, r1, r2, r3, vbase + crow * VSTRB + col * 2);
                mma_16816(o0[gp * 2],     p0 + ks * 4, r0, r1);
                mma_16816(o0[gp * 2 + 1], p0 + ks * 4, r2, r3);
                mma_16816(o1[gp * 2],     p1 + ks * 4, r0, r1);
                mma_16816(o1[gp * 2 + 1], p1 + ks * 4, r2, r3);
            }
        }
        __syncthreads();
    }

    // ---- denominators: lane-quad reduce, then combine m-groups in smem ----
    d0A += __shfl_xor_sync(~0u, d0A, 1); d0A += __shfl_xor_sync(~0u, d0A, 2);
    d0B += __shfl_xor_sync(~0u, d0B, 1); d0B += __shfl_xor_sync(~0u, d0B, 2);
    d1A += __shfl_xor_sync(~0u, d1A, 1); d1A += __shfl_xor_sync(~0u, d1A, 2);
    d1B += __shfl_xor_sync(~0u, d1B, 1); d1B += __shfl_xor_sync(~0u, d1B, 2);

    float* dsm = (float*)(smem + EP_DSM);
    float* rs  = (float*)(smem + EP_RS);
    float* Os  = (float*)(smem + EP_OS);
    int r0w = wrow + (t >> 2);

    if (mg == 0 && (t & 3) == 0) {
        dsm[r0w] = d0A; dsm[r0w + 8] = d0B;
        dsm[r0w + 16] = d1A; dsm[r0w + 24] = d1B;
    }
    // O partials: m-group 0 writes raw
    if (mg == 0) {
#pragma unroll
        for (int g2 = 0; g2 < 8; g2++) {
            int c0 = g2 * 8 + 2 * (t & 3);
            int nA = wrow + (t >> 2);
            Os[c0 * OSTR + nA]            = o0[g2][0];
            Os[(c0 + 1) * OSTR + nA]      = o0[g2][1];
            Os[c0 * OSTR + nA + 8]        = o0[g2][2];
            Os[(c0 + 1) * OSTR + nA + 8]  = o0[g2][3];
            Os[c0 * OSTR + nA + 16]       = o1[g2][0];
            Os[(c0 + 1) * OSTR + nA + 16] = o1[g2][1];
            Os[c0 * OSTR + nA + 24]       = o1[g2][2];
            Os[(c0 + 1) * OSTR + nA + 24] = o1[g2][3];
        }
    }
    __syncthreads();
    // m-group 1 accumulates
    if (mg == 1) {
        if ((t & 3) == 0) {
            dsm[r0w] += d0A; dsm[r0w + 8] += d0B;
            dsm[r0w + 16] += d1A; dsm[r0w + 24] += d1B;
        }
#pragma unroll
        for (int g2 = 0; g2 < 8; g2++) {
            int c0 = g2 * 8 + 2 * (t & 3);
            int nA = wrow + (t >> 2);
            Os[c0 * OSTR + nA]            += o0[g2][0];
            Os[(c0 + 1) * OSTR + nA]      += o0[g2][1];
            Os[c0 * OSTR + nA + 8]        += o0[g2][2];
            Os[(c0 + 1) * OSTR + nA + 8]  += o0[g2][3];
            Os[c0 * OSTR + nA + 16]       += o1[g2][0];
            Os[(c0 + 1) * OSTR + nA + 16] += o1[g2][1];
            Os[c0 * OSTR + nA + 24]       += o1[g2][2];
            Os[(c0 + 1) * OSTR + nA + 24] += o1[g2][3];
        }
    }
    __syncthreads();
    if (tid < NB) rs[tid] = gamma[0] / dsm[tid];
    __syncthreads();

    // ---- coalesced write: out[c][n] = Os*rs + x ----
#pragma unroll
    for (int rr = 0; rr < 8; rr++) {
        int f = tid + 128 * rr;          // float4 id: 64 c-rows x 16 per row
        int c = f >> 4, j4 = f & 15;
        float4 o = *(float4*)&Os[c * OSTR + j4 * 4];
        float4 rv = *(float4*)&rs[j4 * 4];
        size_t base = (size_t)(b * CDIM + c) * N_SP + n0 + j4 * 4;
        float4 xv = *(const float4*)&x[base];
        o.x = fmaf(o.x, rv.x, xv.x);
        o.y = fmaf(o.y, rv.y, xv.y);
        o.z = fmaf(o.z, rv.z, xv.z);
        o.w = fmaf(o.w, rv.w, xv.w);
        *(float4*)&out[base] = o;
    }
}

// ---------------------------------------------------------------------------
extern "C" void kernel_launch(void* const* d_in, const int* in_sizes, int n_in,
                              void* d_out, int out_size)
{
    const float* x     = (const float*)d_in[0];
    const float* Wq    = (const float*)d_in[1];
    const float* bq    = (const float*)d_in[2];
    const float* Wk    = (const float*)d_in[3];
    const float* bk    = (const float*)d_in[4];
    const float* Wv    = (const float*)d_in[5];
    const float* bv    = (const float*)d_in[6];
    const float* gamma = (const float*)d_in[7];
    float* out = (float*)d_out;

    qkv_kernel<<<256, 128>>>(x, Wq, bq, Wk, bk, Wv, bv);
    attn_kernel<<<BDIM * (N_SP / NB), 128>>>(x, gamma, out);
}